// round 14
// baseline (speedup 1.0000x reference)
#include <cuda_runtime.h>
#include <cuda_fp16.h>
#include <cstdint>
#include <math.h>

// ---------------------------------------------------------------------------
// HybridFeedForward, fused persistent pool v3 — ONE tile shape (128x96).
//   prep: TT tables -> dense W1h/W2h (half)
//   fused_mlp (persistent, 296 CTAs, atomic tile counter):
//     tiles: 32 cvt tiles; then per 128-row block: 32 GEMM1 tiles (K=768,
//            gelu, half->H) followed by 8 GEMM2 tiles (K=3072, +b2, fp32->out)
//   Single gemm_tile instantiation => no register blowup (R13 failure mode).
// ---------------------------------------------------------------------------

#define NTOK 4096
#define D_IN 768
#define D_HID 3072
#define NSTAGE 4
#define SBYTES 16384          // per-stage smem: A 8KB + B 8KB
#define FUSED_SMEM (1024 + NSTAGE * SBYTES)

#define NT_CVT 32
#define TPB 40                // per 128-row block: 32 G1 + 8 G2
#define NT_TOTAL (NT_CVT + 32 * TPB)   // 1312

// ---- scratch (device globals; no allocation allowed) ----
__device__ float  g_T12_1[384 * 24];
__device__ float  g_T34_1[24 * 6144];
__device__ float  g_T12_2[384 * 24];
__device__ float  g_T34_2[24 * 6144];
__device__ __half g_W1h[D_IN * D_HID];     // [768][3072] row-major K x N
__device__ __half g_W2h[D_HID * D_IN];     // [3072][768]
__device__ __half g_xh[NTOK * D_IN];
__device__ __half g_H[NTOK * D_HID];
// [0]=tile ctr, [1..32]=x_ready[mb], [33..64]=g1_ready[mb] (to 32)
__device__ int    g_sync[65];

// ---------------------------------------------------------------------------
// helpers
// ---------------------------------------------------------------------------
__device__ __forceinline__ float gelu_erf(float x)
{
    return 0.5f * x * (1.0f + erff(x * 0.70710678118654752f));
}

__device__ __forceinline__ uint32_t smem_u32(const void* p)
{
    uint32_t a;
    asm("{ .reg .u64 t; cvta.to.shared.u64 t, %1; cvt.u32.u64 %0, t; }"
        : "=r"(a) : "l"(p));
    return a;
}

__device__ __forceinline__ void cp16(uint32_t s, const void* g)
{
    asm volatile("cp.async.cg.shared.global [%0], [%1], 16;"
                 :: "r"(s), "l"(g) : "memory");
}

#define MMA_F16(d, a, b)                                                      \
    asm volatile("mma.sync.aligned.m16n8k16.row.col.f32.f16.f16.f32 "         \
                 "{%0,%1,%2,%3}, {%4,%5,%6,%7}, {%8,%9}, {%0,%1,%2,%3};"      \
                 : "+f"(d[0]), "+f"(d[1]), "+f"(d[2]), "+f"(d[3])             \
                 : "r"(a[0]), "r"(a[1]), "r"(a[2]), "r"(a[3]),                \
                   "r"(b[0]), "r"(b[1]))

#define LDSM_X4(r0, r1, r2, r3, addr)                                         \
    asm volatile("ldmatrix.sync.aligned.m8n8.x4.shared.b16 {%0,%1,%2,%3}, [%4];" \
                 : "=r"(r0), "=r"(r1), "=r"(r2), "=r"(r3) : "r"(addr))

#define LDSM_X4T(r0, r1, r2, r3, addr)                                        \
    asm volatile("ldmatrix.sync.aligned.m8n8.x4.trans.shared.b16 {%0,%1,%2,%3}, [%4];" \
                 : "=r"(r0), "=r"(r1), "=r"(r2), "=r"(r3) : "r"(addr))

#define LDSM_X2T(r0, r1, addr)                                                \
    asm volatile("ldmatrix.sync.aligned.m8n8.x2.trans.shared.b16 {%0,%1}, [%2];" \
                 : "=r"(r0), "=r"(r1) : "r"(addr))

// ---------------------------------------------------------------------------
// Stage 1: TT core contraction tables (unchanged, validated)
// ---------------------------------------------------------------------------
__global__ void build_tables(const float* __restrict__ g1, const float* __restrict__ g2,
                             const float* __restrict__ g3, const float* __restrict__ g4,
                             float* __restrict__ T12, float* __restrict__ T34,
                             int I1, int I2, int I3, int I4,
                             int O1, int O2, int O3, int O4)
{
    const int R1 = 12, R2 = 24, R3 = 12;
    int idx = blockIdx.x * blockDim.x + threadIdx.x;
    int n12 = I1 * I2 * O1 * O2 * R2;     // 9216
    int nN  = I3 * I4 * O3 * O4;          // 6144
    if (idx < n12) {
        int r2 = idx % R2; int m = idx / R2;
        int o2 = m % O2; int t = m / O2;
        int o1 = t % O1; t /= O1;
        int i2 = t % I2; int i1 = t / I2;
        float a0 = 0.f, a1 = 0.f, a2 = 0.f, a3 = 0.f;
        #pragma unroll
        for (int r1 = 0; r1 < R1; r1 += 4) {
            a0 += g1[(i1 * O1 + o1) * R1 + r1 + 0] * g2[(((r1 + 0) * I2 + i2) * O2 + o2) * R2 + r2];
            a1 += g1[(i1 * O1 + o1) * R1 + r1 + 1] * g2[(((r1 + 1) * I2 + i2) * O2 + o2) * R2 + r2];
            a2 += g1[(i1 * O1 + o1) * R1 + r1 + 2] * g2[(((r1 + 2) * I2 + i2) * O2 + o2) * R2 + r2];
            a3 += g1[(i1 * O1 + o1) * R1 + r1 + 3] * g2[(((r1 + 3) * I2 + i2) * O2 + o2) * R2 + r2];
        }
        T12[m * R2 + r2] = (a0 + a1) + (a2 + a3);
    } else {
        int j = idx - n12;
        if (j >= R2 * nN) return;
        int n = j % nN; int r2 = j / nN;
        int o4 = n % O4; int t = n / O4;
        int o3 = t % O3; t /= O3;
        int i4 = t % I4; int i3 = t / I4;
        float a0 = 0.f, a1 = 0.f, a2 = 0.f, a3 = 0.f;
        #pragma unroll
        for (int r3 = 0; r3 < R3; r3 += 4) {
            a0 += g3[((r2 * I3 + i3) * O3 + o3) * R3 + r3 + 0] * g4[((r3 + 0) * I4 + i4) * O4 + o4];
            a1 += g3[((r2 * I3 + i3) * O3 + o3) * R3 + r3 + 1] * g4[((r3 + 1) * I4 + i4) * O4 + o4];
            a2 += g3[((r2 * I3 + i3) * O3 + o3) * R3 + r3 + 2] * g4[((r3 + 2) * I4 + i4) * O4 + o4];
            a3 += g3[((r2 * I3 + i3) * O3 + o3) * R3 + r3 + 3] * g4[((r3 + 3) * I4 + i4) * O4 + o4];
        }
        T34[r2 * nN + n] = (a0 + a1) + (a2 + a3);
    }
}

// ---------------------------------------------------------------------------
// Stage 2: dense W build, both layers, half output (unchanged, validated)
// ---------------------------------------------------------------------------
__global__ void __launch_bounds__(256)
build_w2x(const float* __restrict__ T12a, const float* __restrict__ T34a,
          __half* __restrict__ Wa,
          const float* __restrict__ T12b, const float* __restrict__ T34b,
          __half* __restrict__ Wb)
{
    const float* T12;
    const float* T34;
    __half* W;
    int I34, O34, O12, Ncols;
    if (blockIdx.z == 0) {
        T12 = T12a; T34 = T34a; W = Wa;
        I34 = 48; O34 = 128; O12 = 24; Ncols = 3072;
    } else {
        T12 = T12b; T34 = T34b; W = Wb;
        I34 = 128; O34 = 48; O12 = 16; Ncols = 768;
    }

    __shared__ float s12[96 * 24];
    int mbase = blockIdx.y * 96;
    for (int i = threadIdx.x; i < 96 * 24 / 4; i += 256)
        ((float4*)s12)[i] = ((const float4*)(T12 + mbase * 24))[i];
    __syncthreads();

    int nl = threadIdx.x & 63;
    int mg = threadIdx.x >> 6;
    int n  = blockIdx.x * 64 + nl;

    float t34[24];
    #pragma unroll
    for (int r = 0; r < 24; r++) t34[r] = T34[r * 6144 + n];

    int i3i4 = n / O34, o3o4 = n % O34;

    int m0    = mbase + mg * 24;
    int i1i2  = m0 / O12;
    int o1o2  = m0 % O12;
    long addr = (long)(i1i2 * I34 + i3i4) * Ncols + o1o2 * O34 + o3o4;
    const long dWrap = (long)I34 * Ncols - (long)(O12 - 1) * O34;

    const float4* p = (const float4*)&s12[(mg * 24) * 24];
    #pragma unroll 4
    for (int mm = 0; mm < 24; mm++) {
        float a0 = 0.f, a1 = 0.f, a2 = 0.f, a3 = 0.f;
        #pragma unroll
        for (int q = 0; q < 6; q++) {
            float4 v = p[q];
            a0 += v.x * t34[q * 4 + 0];
            a1 += v.y * t34[q * 4 + 1];
            a2 += v.z * t34[q * 4 + 2];
            a3 += v.w * t34[q * 4 + 3];
        }
        p += 6;
        W[addr] = __float2half_rn((a0 + a1) + (a2 + a3));
        o1o2++;
        if (o1o2 == O12) { o1o2 = 0; addr += dWrap; }
        else             { addr += O34; }
    }
}

// ---------------------------------------------------------------------------
// the ONE tile: 128x96, BK=32, runtime K-length / activation / output type
// ---------------------------------------------------------------------------
__device__ __forceinline__ void gemm_tile_12896(
    const __half* __restrict__ A, const __half* __restrict__ B,
    const float* __restrict__ bias, void* __restrict__ Cv,
    const int N, const int Kfull, const int bm, const int bn, const int T,
    const bool gelu, const bool half_out,
    const uint32_t stg, const int tid, const int lane, const int wid)
{
    constexpr int BROWB = 256;
    constexpr int NFRAG = 3;
    constexpr int WN    = 24;

    const int wm = wid & 1;
    const int wn = wid >> 1;

    // drain previous tile's cp.async before smem reuse
    asm volatile("cp.async.wait_group 0;" ::: "memory");
    __syncthreads();

    // ---- A global->smem mapping (row = tid>>1, two 16B chunks) ----
    const int a_rowl = tid >> 1;
    const int ja     = (tid & 1) << 1;
    const uint32_t swa = (a_rowl >> 1) & 3;
    const __half* Ag = A + (size_t)(bm + a_rowl) * Kfull + ja * 8;
    const uint32_t a_st0 = a_rowl * 64 + (((uint32_t)ja ^ swa) << 4);
    const uint32_t a_st1 = a_rowl * 64 + (((uint32_t)(ja + 1) ^ swa) << 4);

    // ---- B global->smem mapping (BN=96: 12 chunks per k-row) ----
    const int bk0 = tid >> 3, bc0 = tid & 7;
    const int bk1 = tid >> 2, bc1 = 8 + (tid & 3);
    const int bp1 = (tid < 128);
    const __half* Bg0 = B + (size_t)bk0 * N + bn + bc0 * 8;
    const __half* Bg1 = B + (size_t)bk1 * N + bn + bc1 * 8;
    const uint32_t b_st0 = bk0 * BROWB + (((uint32_t)bc0 ^ (uint32_t)(bk0 & 7)) << 4);
    const uint32_t b_st1 = bk1 * BROWB + (((uint32_t)bc1 ^ (uint32_t)(bk1 & 7)) << 4);

    auto LOADST = [&](int t, int s) {
        uint32_t sa = stg + s * SBYTES;
        uint32_t sb = sa + 8192;
        const __half* ap = Ag + t * 32;
        cp16(sa + a_st0, ap);
        cp16(sa + a_st1, ap + 8);
        const size_t boff = (size_t)t * 32 * N;
        cp16(sb + b_st0, Bg0 + boff);
        if (bp1) cp16(sb + b_st1, Bg1 + boff);
    };

    // ---- fragment address components ----
    const int lr      = lane & 7;
    const int mi      = lane >> 3;
    const int a_row0  = wm * 64 + ((mi & 1) << 3) + lr;
    const int a_kcbit = (mi >> 1) & 1;
    const int b_kl = ((lane >> 3) & 1) * 8 + (lane & 7);
    const int b_j2 = (lane >> 4) & 1;

    float acc[4][NFRAG][4];
    #pragma unroll
    for (int i = 0; i < 4; i++)
        #pragma unroll
        for (int j = 0; j < NFRAG; j++)
            #pragma unroll
            for (int k = 0; k < 4; k++) acc[i][j][k] = 0.f;

    #pragma unroll
    for (int s = 0; s < NSTAGE - 1; s++) {
        LOADST(s, s);
        asm volatile("cp.async.commit_group;" ::: "memory");
    }

    #pragma unroll 4
    for (int t = 0; t < T; t++) {
        asm volatile("cp.async.wait_group %0;" :: "n"(NSTAGE - 2) : "memory");
        __syncthreads();

        int tl = t + NSTAGE - 1;
        if (tl < T) LOADST(tl, tl & (NSTAGE - 1));
        asm volatile("cp.async.commit_group;" ::: "memory");

        uint32_t sa = stg + (t & (NSTAGE - 1)) * SBYTES;
        uint32_t sb = sa + 8192;

        #pragma unroll
        for (int ks = 0; ks < 2; ks++) {
            uint32_t af[4][4];
            #pragma unroll
            for (int mt = 0; mt < 4; mt++) {
                int r = a_row0 + mt * 16;
                uint32_t kc = (uint32_t)((ks << 1) | a_kcbit);
                uint32_t addr = sa + r * 64 + ((kc ^ ((r >> 1) & 3)) << 4);
                LDSM_X4(af[mt][0], af[mt][1], af[mt][2], af[mt][3], addr);
            }
            uint32_t bf[NFRAG][2];
            {
                int kk = ks * 16 + b_kl;
                uint32_t c0 = (uint32_t)(((wn * WN) >> 3) + b_j2);
                uint32_t ad0 = sb + kk * BROWB + ((c0 ^ (uint32_t)(kk & 7)) << 4);
                uint32_t r0, r1, r2, r3;
                LDSM_X4T(r0, r1, r2, r3, ad0);
                bf[0][0] = r0; bf[0][1] = r1;
                bf[1][0] = r2; bf[1][1] = r3;
                uint32_t c2 = (uint32_t)((wn * WN + 16) >> 3);
                uint32_t ad2 = sb + kk * BROWB + ((c2 ^ (uint32_t)(kk & 7)) << 4);
                LDSM_X2T(bf[2][0], bf[2][1], ad2);
            }
            #pragma unroll
            for (int mt = 0; mt < 4; mt++)
                #pragma unroll
                for (int nt = 0; nt < NFRAG; nt++)
                    MMA_F16(acc[mt][nt], af[mt], bf[nt]);
        }
    }

    // ---- epilogue: bias (+gelu), plain stores ----
    const int g  = lane >> 2;
    const int t4 = lane & 3;
    #pragma unroll
    for (int mt = 0; mt < 4; mt++) {
        int m = bm + wm * 64 + mt * 16 + g;
        #pragma unroll
        for (int nt = 0; nt < NFRAG; nt++) {
            int n = bn + wn * WN + nt * 8 + t4 * 2;
            float bv0 = bias[n], bv1 = bias[n + 1];
            float v0 = acc[mt][nt][0] + bv0;
            float v1 = acc[mt][nt][1] + bv1;
            float v2 = acc[mt][nt][2] + bv0;
            float v3 = acc[mt][nt][3] + bv1;
            if (gelu) {
                v0 = gelu_erf(v0); v1 = gelu_erf(v1);
                v2 = gelu_erf(v2); v3 = gelu_erf(v3);
            }
            if (half_out) {
                __half* Ch = (__half*)Cv;
                *(__half2*)&Ch[(size_t)m * N + n]       = __floats2half2_rn(v0, v1);
                *(__half2*)&Ch[(size_t)(m + 8) * N + n] = __floats2half2_rn(v2, v3);
            } else {
                float* Cf = (float*)Cv;
                *(float2*)&Cf[(size_t)m * N + n]       = make_float2(v0, v1);
                *(float2*)&Cf[(size_t)(m + 8) * N + n] = make_float2(v2, v3);
            }
        }
    }
}

// ---------------------------------------------------------------------------
// persistent fused kernel
// ---------------------------------------------------------------------------
__global__ void __launch_bounds__(256, 2)
fused_mlp(const float4* __restrict__ x4,
          const float* __restrict__ b1,
          const float* __restrict__ b2,
          float* __restrict__ out)
{
    extern __shared__ char dsm[];
    const uint32_t stg = (smem_u32(dsm) + 1023) & ~1023u;
    __shared__ int s_t;

    const int tid  = threadIdx.x;
    const int lane = tid & 31;
    const int wid  = tid >> 5;
    volatile int* vs = (volatile int*)g_sync;

    while (true) {
        if (tid == 0) s_t = atomicAdd(&g_sync[0], 1);
        __syncthreads();
        const int t = s_t;
        if (t >= NT_TOTAL) return;

        if (t < NT_CVT) {
            // convert x rows [t*128, (t+1)*128): 24576 float4
            const int base = t * 24576;
            #pragma unroll 4
            for (int i = 0; i < 96; i++) {
                int idx = base + i * 256 + tid;
                float4 v = x4[idx];
                __half2* o = (__half2*)g_xh + (size_t)idx * 2;
                o[0] = __floats2half2_rn(v.x, v.y);
                o[1] = __floats2half2_rn(v.z, v.w);
            }
            __threadfence();
            __syncthreads();
            if (tid == 0) atomicExch(&g_sync[1 + t], 1);
        } else {
            const int u   = t - NT_CVT;
            const int blk = u / TPB;
            const int r   = u % TPB;
            if (r < 32) {
                // GEMM1 tile: (blk, n=r) 128x96, K=768
                if (tid == 0) {
                    while (vs[1 + blk] == 0) __nanosleep(32);
                    __threadfence();
                }
                __syncthreads();
                gemm_tile_12896(g_xh, g_W1h, b1, g_H,
                                D_HID, D_IN, blk * 128, r * 96, 24,
                                true, true, stg, tid, lane, wid);
                __threadfence();
                __syncthreads();
                if (tid == 0) atomicAdd(&g_sync[33 + blk], 1);
            } else {
                // GEMM2 tile: (blk, n=r-32) 128x96, K=3072
                const int n = r - 32;
                if (tid == 0) {
                    while (vs[33 + blk] < 32) __nanosleep(32);
                    __threadfence();
                }
                __syncthreads();
                gemm_tile_12896(g_H, g_W2h, b2, out,
                                D_IN, D_HID, blk * 128, n * 96, 96,
                                false, false, stg, tid, lane, wid);
                __syncthreads();
            }
        }
    }
}

// ---------------------------------------------------------------------------
// launch
// ---------------------------------------------------------------------------
static void* sym_addr(const void* sym)
{
    void* p = nullptr;
    cudaGetSymbolAddress(&p, sym);
    return p;
}

extern "C" void kernel_launch(void* const* d_in, const int* in_sizes, int n_in,
                              void* d_out, int out_size)
{
    const float* x   = (const float*)d_in[0];
    const float* g1a = (const float*)d_in[1];
    const float* g1b = (const float*)d_in[2];
    const float* g1c = (const float*)d_in[3];
    const float* g1d = (const float*)d_in[4];
    const float* b1  = (const float*)d_in[5];
    const float* g2a = (const float*)d_in[6];
    const float* g2b = (const float*)d_in[7];
    const float* g2c = (const float*)d_in[8];
    const float* g2d = (const float*)d_in[9];
    const float* b2  = (const float*)d_in[10];
    float* out = (float*)d_out;

    float*  T12_1 = (float*)sym_addr(g_T12_1);
    float*  T34_1 = (float*)sym_addr(g_T34_1);
    float*  T12_2 = (float*)sym_addr(g_T12_2);
    float*  T34_2 = (float*)sym_addr(g_T34_2);
    __half* W1h   = (__half*)sym_addr(g_W1h);
    __half* W2h   = (__half*)sym_addr(g_W2h);
    void*   syncp = sym_addr(g_sync);

    cudaFuncSetAttribute(fused_mlp,
                         cudaFuncAttributeMaxDynamicSharedMemorySize, FUSED_SMEM);

    build_tables<<<612, 256>>>(g1a, g1b, g1c, g1d, T12_1, T34_1,
                               4, 4, 6, 8, 4, 6, 8, 16);
    build_tables<<<612, 256>>>(g2a, g2b, g2c, g2d, T12_2, T34_2,
                               4, 6, 8, 16, 4, 4, 6, 8);

    {
        dim3 grid(96, 4, 2);
        build_w2x<<<grid, 256>>>(T12_1, T34_1, W1h, T12_2, T34_2, W2h);
    }

    // reset tile counter + ready flags (every graph replay)
    cudaMemsetAsync(syncp, 0, sizeof(int) * 65);

    fused_mlp<<<296, 256, FUSED_SMEM>>>((const float4*)x, b1, b2, out);
}

// round 17
// speedup vs baseline: 1.4157x; 1.4157x over previous
#include <cuda_runtime.h>
#include <cuda_fp16.h>
#include <cstdint>
#include <math.h>

// ---------------------------------------------------------------------------
// HybridFeedForward: TT cores -> dense W1/W2 (half, row-major [K][N]) ->
// fp16 mma.sync GEMMs with B row-major via ldmatrix.trans.
//   GEMM1: H = gelu(x @ W1 + b1)   (4096 x 3072, K=768)   tile 128x96, 1024 CTAs
//   GEMM2: y = H @ W2 + b2         (4096 x 768,  K=3072)  tile 128x96,  256 CTAs
// Prep merged into 2 launches (tables2x; W-build + x-convert).
// ---------------------------------------------------------------------------

#define NTOK 4096
#define D_IN 768
#define D_HID 3072
#define NSTAGE 4

// ---- scratch (device globals; no allocation allowed) ----
__device__ float  g_T12_1[384 * 24];
__device__ float  g_T34_1[24 * 6144];
__device__ float  g_T12_2[384 * 24];
__device__ float  g_T34_2[24 * 6144];
__device__ __half g_W1h[D_IN * D_HID];     // W1 [768][3072] row-major K x N
__device__ __half g_W2h[D_HID * D_IN];     // W2 [3072][768]
__device__ __half g_xh[NTOK * D_IN];       // x in half
__device__ __half g_H[NTOK * D_HID];       // hidden, half

// ---------------------------------------------------------------------------
// helpers
// ---------------------------------------------------------------------------
__device__ __forceinline__ float gelu_erf(float x)
{
    return 0.5f * x * (1.0f + erff(x * 0.70710678118654752f));
}

__device__ __forceinline__ uint32_t smem_u32(const void* p)
{
    uint32_t a;
    asm("{ .reg .u64 t; cvta.to.shared.u64 t, %1; cvt.u32.u64 %0, t; }"
        : "=r"(a) : "l"(p));
    return a;
}

// ---------------------------------------------------------------------------
// Stage 1: TT tables, BOTH layers in one launch (blockIdx.y selects layer)
// ---------------------------------------------------------------------------
__global__ void build_tables2x(
    const float* __restrict__ g1a, const float* __restrict__ g1b,
    const float* __restrict__ g1c, const float* __restrict__ g1d,
    float* __restrict__ T12a, float* __restrict__ T34a,
    const float* __restrict__ g2a, const float* __restrict__ g2b,
    const float* __restrict__ g2c, const float* __restrict__ g2d,
    float* __restrict__ T12b, float* __restrict__ T34b)
{
    const int R1 = 12, R2 = 24, R3 = 12;
    const float *g1, *g2, *g3, *g4;
    float *T12, *T34;
    int I1, I2, I3, I4, O1, O2, O3, O4;
    if (blockIdx.y == 0) {
        g1 = g1a; g2 = g1b; g3 = g1c; g4 = g1d; T12 = T12a; T34 = T34a;
        I1 = 4; I2 = 4; I3 = 6; I4 = 8; O1 = 4; O2 = 6; O3 = 8; O4 = 16;
    } else {
        g1 = g2a; g2 = g2b; g3 = g2c; g4 = g2d; T12 = T12b; T34 = T34b;
        I1 = 4; I2 = 6; I3 = 8; I4 = 16; O1 = 4; O2 = 4; O3 = 6; O4 = 8;
    }

    int idx = blockIdx.x * blockDim.x + threadIdx.x;
    int n12 = I1 * I2 * O1 * O2 * R2;     // 9216
    int nN  = I3 * I4 * O3 * O4;          // 6144
    if (idx < n12) {
        int r2 = idx % R2; int m = idx / R2;
        int o2 = m % O2; int t = m / O2;
        int o1 = t % O1; t /= O1;
        int i2 = t % I2; int i1 = t / I2;
        float a0 = 0.f, a1 = 0.f, a2 = 0.f, a3 = 0.f;
        #pragma unroll
        for (int r1 = 0; r1 < R1; r1 += 4) {
            a0 += g1[(i1 * O1 + o1) * R1 + r1 + 0] * g2[(((r1 + 0) * I2 + i2) * O2 + o2) * R2 + r2];
            a1 += g1[(i1 * O1 + o1) * R1 + r1 + 1] * g2[(((r1 + 1) * I2 + i2) * O2 + o2) * R2 + r2];
            a2 += g1[(i1 * O1 + o1) * R1 + r1 + 2] * g2[(((r1 + 2) * I2 + i2) * O2 + o2) * R2 + r2];
            a3 += g1[(i1 * O1 + o1) * R1 + r1 + 3] * g2[(((r1 + 3) * I2 + i2) * O2 + o2) * R2 + r2];
        }
        T12[m * R2 + r2] = (a0 + a1) + (a2 + a3);
    } else {
        int j = idx - n12;
        if (j >= R2 * nN) return;
        int n = j % nN; int r2 = j / nN;
        int o4 = n % O4; int t = n / O4;
        int o3 = t % O3; t /= O3;
        int i4 = t % I4; int i3 = t / I4;
        float a0 = 0.f, a1 = 0.f, a2 = 0.f, a3 = 0.f;
        #pragma unroll
        for (int r3 = 0; r3 < R3; r3 += 4) {
            a0 += g3[((r2 * I3 + i3) * O3 + o3) * R3 + r3 + 0] * g4[((r3 + 0) * I4 + i4) * O4 + o4];
            a1 += g3[((r2 * I3 + i3) * O3 + o3) * R3 + r3 + 1] * g4[((r3 + 1) * I4 + i4) * O4 + o4];
            a2 += g3[((r2 * I3 + i3) * O3 + o3) * R3 + r3 + 2] * g4[((r3 + 2) * I4 + i4) * O4 + o4];
            a3 += g3[((r2 * I3 + i3) * O3 + o3) * R3 + r3 + 3] * g4[((r3 + 3) * I4 + i4) * O4 + o4];
        }
        T34[r2 * nN + n] = (a0 + a1) + (a2 + a3);
    }
}

// ---------------------------------------------------------------------------
// Stage 2: z=0/1 -> dense W build (half out); z=2 -> x fp32->fp16 convert.
// W-build is L1/FMA-bound, cvt is DRAM-bound: they overlap in one launch.
// ---------------------------------------------------------------------------
__global__ void __launch_bounds__(256)
build_w_cvt(const float* __restrict__ T12a, const float* __restrict__ T34a,
            __half* __restrict__ Wa,
            const float* __restrict__ T12b, const float* __restrict__ T34b,
            __half* __restrict__ Wb,
            const float4* __restrict__ x4, __half2* __restrict__ xh2)
{
    __shared__ float s12[96 * 24];

    if (blockIdx.z == 2) {
        // x convert: 384 blocks x 2048 float4 each = 786432 float4 total
        const int b = blockIdx.y * 96 + blockIdx.x;
        const int base = b * 2048;
        #pragma unroll 4
        for (int i = threadIdx.x; i < 2048; i += 256) {
            int idx = base + i;
            float4 v = x4[idx];
            xh2[2 * idx + 0] = __floats2half2_rn(v.x, v.y);
            xh2[2 * idx + 1] = __floats2half2_rn(v.z, v.w);
        }
        return;
    }

    const float* T12;
    const float* T34;
    __half* W;
    int I34, O34, O12, Ncols;
    if (blockIdx.z == 0) {
        T12 = T12a; T34 = T34a; W = Wa;
        I34 = 48; O34 = 128; O12 = 24; Ncols = 3072;
    } else {
        T12 = T12b; T34 = T34b; W = Wb;
        I34 = 128; O34 = 48; O12 = 16; Ncols = 768;
    }

    int mbase = blockIdx.y * 96;
    for (int i = threadIdx.x; i < 96 * 24 / 4; i += 256)
        ((float4*)s12)[i] = ((const float4*)(T12 + mbase * 24))[i];
    __syncthreads();

    int nl = threadIdx.x & 63;
    int mg = threadIdx.x >> 6;
    int n  = blockIdx.x * 64 + nl;

    float t34[24];
    #pragma unroll
    for (int r = 0; r < 24; r++) t34[r] = T34[r * 6144 + n];

    int i3i4 = n / O34, o3o4 = n % O34;

    int m0    = mbase + mg * 24;
    int i1i2  = m0 / O12;
    int o1o2  = m0 % O12;
    long addr = (long)(i1i2 * I34 + i3i4) * Ncols + o1o2 * O34 + o3o4;
    const long dWrap = (long)I34 * Ncols - (long)(O12 - 1) * O34;

    const float4* p = (const float4*)&s12[(mg * 24) * 24];
    #pragma unroll 4
    for (int mm = 0; mm < 24; mm++) {
        float a0 = 0.f, a1 = 0.f, a2 = 0.f, a3 = 0.f;
        #pragma unroll
        for (int q = 0; q < 6; q++) {
            float4 v = p[q];
            a0 += v.x * t34[q * 4 + 0];
            a1 += v.y * t34[q * 4 + 1];
            a2 += v.z * t34[q * 4 + 2];
            a3 += v.w * t34[q * 4 + 3];
        }
        p += 6;
        W[addr] = __float2half_rn((a0 + a1) + (a2 + a3));
        o1o2++;
        if (o1o2 == O12) { o1o2 = 0; addr += dWrap; }
        else             { addr += O34; }
    }
}

// ---------------------------------------------------------------------------
// fp16 GEMM: C = act(A @ B + bias)
//   A: M x K row-major half;  B: K x N row-major half (ldmatrix.trans path)
//   CTA tile 128 x BN, BK=32, 4-stage cp.async, 8 warps (2m x 4n).
// smem per stage:
//   A[128][32] half, 64B rows, chunk swizzle  c ^= (row>>1)&3
//   B[32 rows][256B], 16B chunk swizzle       c ^= (k&7)      (BN<=128)
// ---------------------------------------------------------------------------
#define MMA_F16(d, a, b)                                                      \
    asm volatile("mma.sync.aligned.m16n8k16.row.col.f32.f16.f16.f32 "         \
                 "{%0,%1,%2,%3}, {%4,%5,%6,%7}, {%8,%9}, {%0,%1,%2,%3};"      \
                 : "+f"(d[0]), "+f"(d[1]), "+f"(d[2]), "+f"(d[3])             \
                 : "r"(a[0]), "r"(a[1]), "r"(a[2]), "r"(a[3]),                \
                   "r"(b[0]), "r"(b[1]))

#define LDSM_X4(r0, r1, r2, r3, addr)                                         \
    asm volatile("ldmatrix.sync.aligned.m8n8.x4.shared.b16 {%0,%1,%2,%3}, [%4];" \
                 : "=r"(r0), "=r"(r1), "=r"(r2), "=r"(r3) : "r"(addr))

#define LDSM_X4T(r0, r1, r2, r3, addr)                                        \
    asm volatile("ldmatrix.sync.aligned.m8n8.x4.trans.shared.b16 {%0,%1,%2,%3}, [%4];" \
                 : "=r"(r0), "=r"(r1), "=r"(r2), "=r"(r3) : "r"(addr))

#define LDSM_X2T(r0, r1, addr)                                                \
    asm volatile("ldmatrix.sync.aligned.m8n8.x2.trans.shared.b16 {%0,%1}, [%2];" \
                 : "=r"(r0), "=r"(r1) : "r"(addr))

template <int BN, bool GELU, bool HALF_OUT>
__global__ void __launch_bounds__(256, 2)
gemm_h(const __half* __restrict__ A, const __half* __restrict__ B,
       const float* __restrict__ bias, void* __restrict__ Cv,
       int M, int N, int K)
{
    constexpr int SBYTES = 8192 + 8192;      // A stage + B stage (B rows padded 256B)
    constexpr int NFRAG  = BN / 32;          // n-fragments (8 wide) per warp
    constexpr int WN     = BN / 4;           // warp n-tile

    extern __shared__ char dsm[];
    uint32_t stg = (smem_u32(dsm) + 1023) & ~1023u;

    const int tid  = threadIdx.x;
    const int lane = tid & 31;
    const int wid  = tid >> 5;
    const int wm   = wid & 1;          // 2 warps along M (64 each)
    const int wn   = wid >> 1;         // 4 warps along N (WN each)
    const int bm   = blockIdx.y * 128;
    const int bn   = blockIdx.x * BN;
    const int T    = K >> 5;

    // ---- A global->smem: row = tid>>1, two 16B chunks each ----
    const int a_rowl = tid >> 1;
    const int jj     = tid & 1;
    const uint32_t swa = (a_rowl >> 1) & 3;
    const __half* Ag = A + (size_t)(bm + a_rowl) * K;
    uint32_t a_st[2];
    #pragma unroll
    for (int q = 0; q < 2; q++) {
        uint32_t c = (jj << 1) + q;
        a_st[q] = a_rowl * 64 + ((c ^ swa) << 4);
    }

    // ---- B global->smem: rows are k (32 per tile), row-major N ----
    // BN==128: kr = tid>>3, chunks c = (tid&7)*2 + q          (16 chunks/row)
    // BN==96 : part0 kr = tid>>3, c = tid&7 ; part1 (tid<128) kr = tid>>2, c = 8+(tid&3)
    const int b_kr0 = tid >> 3;
    const int b_kr1 = tid >> 2;                 // BN==96 part1
    const __half* Bg0 = B + (size_t)b_kr0 * N + bn;
    const __half* Bg1 = B + (size_t)b_kr1 * N + bn;

    #define LOADST(t, s)                                                           \
    do {                                                                           \
        uint32_t sa = stg + (s) * SBYTES;                                          \
        uint32_t sb = sa + 8192;                                                   \
        const __half* ap = Ag + (t) * 32 + (jj << 1) * 8;                          \
        _Pragma("unroll")                                                          \
        for (int q = 0; q < 2; q++)                                                \
            asm volatile("cp.async.cg.shared.global [%0], [%1], 16;"               \
                         :: "r"(sa + a_st[q]), "l"(ap + q * 8) : "memory");        \
        const __half* bp = Bg0 + (size_t)(t) * 32 * N;                             \
        if (BN == 128) {                                                           \
            _Pragma("unroll")                                                      \
            for (int q = 0; q < 2; q++) {                                          \
                uint32_t c = ((tid & 7) << 1) + q;                                 \
                asm volatile("cp.async.cg.shared.global [%0], [%1], 16;"           \
                    :: "r"(sb + b_kr0 * 256 + ((c ^ (b_kr0 & 7)) << 4)),           \
                       "l"(bp + c * 8) : "memory");                                \
            }                                                                      \
        } else {                                                                   \
            uint32_t c = tid & 7;                                                  \
            asm volatile("cp.async.cg.shared.global [%0], [%1], 16;"               \
                :: "r"(sb + b_kr0 * 256 + ((c ^ (b_kr0 & 7)) << 4)),               \
                   "l"(bp + c * 8) : "memory");                                    \
            if (tid < 128) {                                                       \
                uint32_t c2 = 8 + (tid & 3);                                       \
                const __half* bp1 = Bg1 + (size_t)(t) * 32 * N;                    \
                asm volatile("cp.async.cg.shared.global [%0], [%1], 16;"           \
                    :: "r"(sb + b_kr1 * 256 + ((c2 ^ (b_kr1 & 7)) << 4)),          \
                       "l"(bp1 + c2 * 8) : "memory");                              \
            }                                                                      \
        }                                                                          \
    } while (0)

    // ---- A fragment address components ----
    const int lr      = lane & 7;
    const int mi      = lane >> 3;
    const int a_row0  = wm * 64 + ((mi & 1) << 3) + lr;
    const int a_kcbit = (mi >> 1) & 1;

    // ---- B fragment (ldmatrix.trans) per-lane components ----
    const int b_kl = ((lane >> 3) & 1) * 8 + (lane & 7);   // k within 16
    const int b_j2 = (lane >> 4) & 1;                      // n +8 (x4 only)

    float acc[4][NFRAG][4];
    #pragma unroll
    for (int i = 0; i < 4; i++)
        #pragma unroll
        for (int j = 0; j < NFRAG; j++)
            #pragma unroll
            for (int k = 0; k < 4; k++) acc[i][j][k] = 0.f;

    // ---- prologue ----
    #pragma unroll
    for (int s = 0; s < NSTAGE - 1; s++) {
        LOADST(s, s);
        asm volatile("cp.async.commit_group;" ::: "memory");
    }

    for (int t = 0; t < T; t++) {
        asm volatile("cp.async.wait_group %0;" :: "n"(NSTAGE - 2) : "memory");
        __syncthreads();

        int tl = t + NSTAGE - 1;
        if (tl < T) LOADST(tl, tl & (NSTAGE - 1));
        asm volatile("cp.async.commit_group;" ::: "memory");

        uint32_t sa = stg + (t & (NSTAGE - 1)) * SBYTES;
        uint32_t sb = sa + 8192;

        #pragma unroll
        for (int ks = 0; ks < 2; ks++) {
            uint32_t af[4][4];
            #pragma unroll
            for (int mt = 0; mt < 4; mt++) {
                int r = a_row0 + mt * 16;
                uint32_t kc = (uint32_t)((ks << 1) | a_kcbit);
                uint32_t addr = sa + r * 64 + ((kc ^ ((r >> 1) & 3)) << 4);
                LDSM_X4(af[mt][0], af[mt][1], af[mt][2], af[mt][3], addr);
            }
            uint32_t bf[NFRAG][2];
            {
                int kk = ks * 16 + b_kl;
                #pragma unroll
                for (int p = 0; p < NFRAG / 2; p++) {
                    uint32_t c = (uint32_t)(((wn * WN + p * 16) >> 3) + b_j2);
                    uint32_t addr = sb + kk * 256 + ((c ^ (uint32_t)(kk & 7)) << 4);
                    uint32_t r0, r1, r2, r3;
                    LDSM_X4T(r0, r1, r2, r3, addr);
                    bf[2 * p][0] = r0;     bf[2 * p][1] = r1;
                    bf[2 * p + 1][0] = r2; bf[2 * p + 1][1] = r3;
                }
                if (NFRAG & 1) {
                    uint32_t c = (uint32_t)((wn * WN + (NFRAG - 1) * 8) >> 3);
                    uint32_t addr = sb + kk * 256 + ((c ^ (uint32_t)(kk & 7)) << 4);
                    LDSM_X2T(bf[NFRAG - 1][0], bf[NFRAG - 1][1], addr);
                }
            }
            #pragma unroll
            for (int mt = 0; mt < 4; mt++)
                #pragma unroll
                for (int nt = 0; nt < NFRAG; nt++)
                    MMA_F16(acc[mt][nt], af[mt], bf[nt]);
        }
    }

    // ---- epilogue: bias (+GELU), store ----
    const int g  = lane >> 2;
    const int t4 = lane & 3;
    #pragma unroll
    for (int mt = 0; mt < 4; mt++) {
        int m = bm + wm * 64 + mt * 16 + g;
        #pragma unroll
        for (int nt = 0; nt < NFRAG; nt++) {
            int n = bn + wn * WN + nt * 8 + t4 * 2;
            float bv0 = bias[n], bv1 = bias[n + 1];
            float v0 = acc[mt][nt][0] + bv0;
            float v1 = acc[mt][nt][1] + bv1;
            float v2 = acc[mt][nt][2] + bv0;
            float v3 = acc[mt][nt][3] + bv1;
            if (GELU) {
                v0 = gelu_erf(v0); v1 = gelu_erf(v1);
                v2 = gelu_erf(v2); v3 = gelu_erf(v3);
            }
            if (HALF_OUT) {
                __half* Ch = (__half*)Cv;
                *(__half2*)&Ch[(size_t)m * N + n]       = __floats2half2_rn(v0, v1);
                *(__half2*)&Ch[(size_t)(m + 8) * N + n] = __floats2half2_rn(v2, v3);
            } else {
                float* Cf = (float*)Cv;
                *(float2*)&Cf[(size_t)m * N + n]       = make_float2(v0, v1);
                *(float2*)&Cf[(size_t)(m + 8) * N + n] = make_float2(v2, v3);
            }
        }
    }
    #undef LOADST
}

// ---------------------------------------------------------------------------
// launch
// ---------------------------------------------------------------------------
static void* sym_addr(const void* sym)
{
    void* p = nullptr;
    cudaGetSymbolAddress(&p, sym);
    return p;
}

extern "C" void kernel_launch(void* const* d_in, const int* in_sizes, int n_in,
                              void* d_out, int out_size)
{
    const float* x   = (const float*)d_in[0];
    const float* g1a = (const float*)d_in[1];
    const float* g1b = (const float*)d_in[2];
    const float* g1c = (const float*)d_in[3];
    const float* g1d = (const float*)d_in[4];
    const float* b1  = (const float*)d_in[5];
    const float* g2a = (const float*)d_in[6];
    const float* g2b = (const float*)d_in[7];
    const float* g2c = (const float*)d_in[8];
    const float* g2d = (const float*)d_in[9];
    const float* b2  = (const float*)d_in[10];
    float* out = (float*)d_out;

    float*  T12_1 = (float*)sym_addr(g_T12_1);
    float*  T34_1 = (float*)sym_addr(g_T34_1);
    float*  T12_2 = (float*)sym_addr(g_T12_2);
    float*  T34_2 = (float*)sym_addr(g_T34_2);
    __half* W1h   = (__half*)sym_addr(g_W1h);
    __half* W2h   = (__half*)sym_addr(g_W2h);
    __half* xh    = (__half*)sym_addr(g_xh);
    __half* H     = (__half*)sym_addr(g_H);

    const int SMEM = 1024 + NSTAGE * 16384;   // 66.5 KB
    cudaFuncSetAttribute(gemm_h<96, true, true>,
                         cudaFuncAttributeMaxDynamicSharedMemorySize, SMEM);
    cudaFuncSetAttribute(gemm_h<96, false, false>,
                         cudaFuncAttributeMaxDynamicSharedMemorySize, SMEM);

    // TT tables, both layers, one launch
    {
        dim3 grid(612, 2);
        build_tables2x<<<grid, 256>>>(g1a, g1b, g1c, g1d, T12_1, T34_1,
                                      g2a, g2b, g2c, g2d, T12_2, T34_2);
    }

    // W1h/W2h build + x->half convert, one launch (z = 0/1/2)
    {
        dim3 grid(96, 4, 3);
        build_w_cvt<<<grid, 256>>>(T12_1, T34_1, W1h, T12_2, T34_2, W2h,
                                   (const float4*)x, (__half2*)xh);
    }

    // GEMM1: H = gelu(xh @ W1 + b1)   tile 128x96, grid 32x32 = 1024 CTAs
    {
        dim3 grid(D_HID / 96, NTOK / 128);
        gemm_h<96, true, true><<<grid, 256, SMEM>>>(xh, W1h, b1, H,
                                                    NTOK, D_HID, D_IN);
    }
    // GEMM2: out = H @ W2 + b2        tile 128x96, grid 8x32 = 256 CTAs
    {
        dim3 grid(D_IN / 96, NTOK / 128);
        gemm_h<96, false, false><<<grid, 256, SMEM>>>(H, W2h, b2, out,
                                                      NTOK, D_IN, D_HID);
    }
}